// round 7
// baseline (speedup 1.0000x reference)
#include <cuda_runtime.h>
#include <cuda_bf16.h>

#define NN     4096
#define WORDS  64
#define HID    256
#define VOCAB  50257
#define NCLASS 4
#define NLEAF  2048

#define GSCAN  64      // persistent scan blocks (all co-resident; multiple of 8 so each
                       // block keeps a fixed 32-row U-slice -> L1-warm across levels)
#define NB     4       // nodes per task (U-row register reuse)

// ---------------- scratch (device globals; no mallocs allowed) ----------------
__device__ float d_ET[(size_t)VOCAB * HID];   // E transposed: [VOCAB][HID]
__device__ float d_X [(size_t)NN * HID];
__device__ float d_Yz[(size_t)NN * HID];
__device__ float d_Yr[(size_t)NN * HID];
__device__ float d_Yh[(size_t)NN * HID];
__device__ float d_H [(size_t)NN * HID];
__device__ float d_Z [(size_t)NN * HID];
__device__ float d_Ubuf[(size_t)NN * HID];
__device__ int   d_par[NN];
__device__ int   d_order[NN];
__device__ int   d_level_start[NN + 1];
__device__ int   d_offs[NN];
__device__ int   d_nlevels;
__device__ unsigned d_bar_cnt;
__device__ unsigned d_bar_gen;
__device__ float d_Pmax[16 * HID];

// ---------------- E transpose: E(HID,VOCAB) -> ET(VOCAB,HID) ----------------
__global__ void transposeE(const float* __restrict__ E) {
    __shared__ float tile[32][33];
    int v0 = blockIdx.x * 32, h0 = blockIdx.y * 32;
    int x = threadIdx.x, y = threadIdx.y;   // 32 x 8
    #pragma unroll
    for (int i = 0; i < 32; i += 8) {
        int h = h0 + y + i, v = v0 + x;
        tile[y + i][x] = (v < VOCAB) ? E[(size_t)h * VOCAB + v] : 0.f;
    }
    __syncthreads();
    #pragma unroll
    for (int i = 0; i < 32; i += 8) {
        int v = v0 + y + i;
        if (v < VOCAB) d_ET[(size_t)v * HID + h0 + x] = tile[x][y + i];
    }
}

// ---------------- X[n,h] = sum_w ET[tree[n,w], h];  also H[0] = X[0] ----------------
__global__ void gatherX(const int* __restrict__ tree) {
    __shared__ int wv[WORDS];
    int n = blockIdx.x;
    if (threadIdx.x < WORDS) wv[threadIdx.x] = tree[n * WORDS + threadIdx.x];
    __syncthreads();
    int h = threadIdx.x;
    float acc = 0.f;
    #pragma unroll 8
    for (int w = 0; w < WORDS; w++) acc += d_ET[(size_t)wv[w] * HID + h];
    d_X[(size_t)n * HID + h] = acc;
    if (n == 0) d_H[h] = acc;   // node_h0[0] = X[0]
}

// ---------------- Y{z,r,h} = X @ W{z,r,h}^T  (4096x256 @ 256x256) ----------------
__global__ void gemm3(const float* __restrict__ Wz, const float* __restrict__ Wr,
                      const float* __restrict__ Wh) {
    const float* W = (blockIdx.z == 0) ? Wz : (blockIdx.z == 1) ? Wr : Wh;
    float* Y       = (blockIdx.z == 0) ? d_Yz : (blockIdx.z == 1) ? d_Yr : d_Yh;
    __shared__ float As[128][17];
    __shared__ float Bs[64][17];
    const int tid = threadIdx.x;
    const int tx = tid & 15, ty = tid >> 4;       // 16x16 thread grid
    const int bm = blockIdx.x, bn = blockIdx.y;
    float acc[8][4];
    #pragma unroll
    for (int i = 0; i < 8; i++)
        #pragma unroll
        for (int j = 0; j < 4; j++) acc[i][j] = 0.f;

    const int arow = tid >> 1, ac8 = (tid & 1) * 8;
    const int brow = tid >> 2, bc4 = (tid & 3) * 4;

    for (int k0 = 0; k0 < HID; k0 += 16) {
        float4 va = *(const float4*)(d_X + (size_t)(bm * 128 + arow) * HID + k0 + ac8);
        float4 vb = *(const float4*)(d_X + (size_t)(bm * 128 + arow) * HID + k0 + ac8 + 4);
        As[arow][ac8 + 0] = va.x; As[arow][ac8 + 1] = va.y;
        As[arow][ac8 + 2] = va.z; As[arow][ac8 + 3] = va.w;
        As[arow][ac8 + 4] = vb.x; As[arow][ac8 + 5] = vb.y;
        As[arow][ac8 + 6] = vb.z; As[arow][ac8 + 7] = vb.w;
        float4 wb = *(const float4*)(W + (size_t)(bn * 64 + brow) * HID + k0 + bc4);
        Bs[brow][bc4 + 0] = wb.x; Bs[brow][bc4 + 1] = wb.y;
        Bs[brow][bc4 + 2] = wb.z; Bs[brow][bc4 + 3] = wb.w;
        __syncthreads();
        #pragma unroll
        for (int kk = 0; kk < 16; kk++) {
            float a[8], b[4];
            #pragma unroll
            for (int i = 0; i < 8; i++) a[i] = As[ty * 8 + i][kk];
            #pragma unroll
            for (int j = 0; j < 4; j++) b[j] = Bs[tx * 4 + j][kk];
            #pragma unroll
            for (int i = 0; i < 8; i++)
                #pragma unroll
                for (int j = 0; j < 4; j++) acc[i][j] = fmaf(a[i], b[j], acc[i][j]);
        }
        __syncthreads();
    }
    #pragma unroll
    for (int i = 0; i < 8; i++) {
        int m = bm * 128 + ty * 8 + i;
        float4 o = make_float4(acc[i][0], acc[i][1], acc[i][2], acc[i][3]);
        *(float4*)(Y + (size_t)m * HID + bn * 64 + tx * 4) = o;
    }
}

// ---------------- prep: levels (pointer doubling) + counting sort; reset barrier ----------------
__global__ void prep(const int* __restrict__ edge) {
    __shared__ int s_jump[NN];
    __shared__ int s_add[NN];
    __shared__ int s_scan[1024];
    __shared__ int s_maxl;
    const int tid = threadIdx.x;
    if (tid == 0) { s_maxl = 0; d_bar_cnt = 0; d_bar_gen = 0; }
    for (int i = tid; i < NN; i += 1024) {
        int p = edge[2 * i];
        d_par[i]  = p;
        s_jump[i] = (i == 0) ? 0 : p;
        s_add[i]  = (i == 0) ? 0 : 1;
    }
    __syncthreads();
    for (int r = 0; r < 12; r++) {
        int nj[4], na[4];
        #pragma unroll
        for (int k = 0; k < 4; k++) {
            int i = tid + k * 1024;
            int j = s_jump[i];
            nj[k] = s_jump[j];
            na[k] = s_add[i] + s_add[j];
        }
        __syncthreads();
        #pragma unroll
        for (int k = 0; k < 4; k++) {
            int i = tid + k * 1024;
            s_jump[i] = nj[k];
            s_add[i]  = na[k];
        }
        __syncthreads();
    }
    // s_add[i] == level(i). Histogram into s_jump (reused).
    for (int i = tid; i < NN; i += 1024) s_jump[i] = 0;
    __syncthreads();
    #pragma unroll
    for (int k = 0; k < 4; k++) {
        int i = tid + k * 1024;
        atomicMax(&s_maxl, s_add[i]);
        atomicAdd(&s_jump[s_add[i]], 1);
    }
    __syncthreads();
    int c0 = s_jump[4 * tid], c1 = s_jump[4 * tid + 1];
    int c2 = s_jump[4 * tid + 2], c3 = s_jump[4 * tid + 3];
    int part = c0 + c1 + c2 + c3;
    s_scan[tid] = part;
    __syncthreads();
    for (int off = 1; off < 1024; off <<= 1) {
        int v = (tid >= off) ? s_scan[tid - off] : 0;
        __syncthreads();
        s_scan[tid] += v;
        __syncthreads();
    }
    int basep = s_scan[tid] - part;
    d_level_start[4 * tid]     = basep;
    d_level_start[4 * tid + 1] = basep + c0;
    d_level_start[4 * tid + 2] = basep + c0 + c1;
    d_level_start[4 * tid + 3] = basep + c0 + c1 + c2;
    d_offs[4 * tid]     = basep;
    d_offs[4 * tid + 1] = basep + c0;
    d_offs[4 * tid + 2] = basep + c0 + c1;
    d_offs[4 * tid + 3] = basep + c0 + c1 + c2;
    if (tid == 0) d_level_start[NN] = NN;
    __syncthreads();
    #pragma unroll
    for (int k = 0; k < 4; k++) {
        int i = tid + k * 1024;
        int lvl = s_add[i];
        int pos = atomicAdd(&d_offs[lvl], 1);
        d_order[pos] = i;
    }
    if (tid == 0) d_nlevels = s_maxl + 1;
}

// ---------------- persistent level-ordered GRU scan ----------------
__device__ __forceinline__ void grid_barrier(unsigned* gen_local) {
    __syncthreads();
    if (threadIdx.x == 0) {
        unsigned target = *gen_local + 1;
        __threadfence();
        unsigned old = atomicAdd(&d_bar_cnt, 1);
        if (old == GSCAN - 1) {
            d_bar_cnt = 0;
            __threadfence();
            atomicExch(&d_bar_gen, target);
        } else {
            volatile unsigned* vg = &d_bar_gen;
            while (*vg < target) { __nanosleep(64); }
        }
        __threadfence();
    }
    __syncthreads();
    (*gen_local)++;
}

__device__ __forceinline__ float sigm(float x) { return 1.f / (1.f + __expf(-x)); }

__global__ void __launch_bounds__(256, 1)
scan_kernel(const float* __restrict__ Uz, const float* __restrict__ Ur,
            const float* __restrict__ Uh, const float* __restrict__ bz,
            const float* __restrict__ br, const float* __restrict__ bh) {
    __shared__ float sv[NB][HID];
    const int tid = threadIdx.x;
    const int sub = tid & 7;        // 8 lanes per row
    const int rrel = tid >> 3;      // 0..31 row within chunk
    unsigned gen = 0;
    const int nlev = d_nlevels;

    for (int L = 1; L < nlev; L++) {
        const int s = d_level_start[L];
        const int e = d_level_start[L + 1];
        const int ngroups = (e - s + NB - 1) / NB;
        const int ntasks = ngroups * 8;     // 8 chunks of 32 rows

        // ---- phase 1: z, r, gate vector u = ph*r ----
        for (int t = blockIdx.x; t < ntasks; t += GSCAN) {
            const int group = t >> 3, chunk = t & 7;
            const int base = s + group * NB;
            const int nb = min(NB, e - base);
            for (int idx = tid; idx < NB * HID; idx += 256) {
                const int j = idx >> 8, c = idx & 255;
                float v = 0.f;
                if (j < nb) {
                    int node = d_order[base + j];
                    v = d_H[(size_t)d_par[node] * HID + c];
                }
                sv[j][c] = v;
            }
            __syncthreads();
            const int r0 = chunk * 32 + rrel;
            float az[NB], ar[NB];
            #pragma unroll
            for (int j = 0; j < NB; j++) { az[j] = 0.f; ar[j] = 0.f; }
            const float* uzr = Uz + (size_t)r0 * HID + sub * 4;
            const float* urr = Ur + (size_t)r0 * HID + sub * 4;
            #pragma unroll
            for (int k = 0; k < 8; k++) {
                const float4 a = *(const float4*)(uzr + k * 32);
                const float4 b = *(const float4*)(urr + k * 32);
                #pragma unroll
                for (int j = 0; j < NB; j++) {
                    const float4 p = *(const float4*)(&sv[j][sub * 4 + k * 32]);
                    az[j] = fmaf(a.x, p.x, fmaf(a.y, p.y, fmaf(a.z, p.z, fmaf(a.w, p.w, az[j]))));
                    ar[j] = fmaf(b.x, p.x, fmaf(b.y, p.y, fmaf(b.z, p.z, fmaf(b.w, p.w, ar[j]))));
                }
            }
            #pragma unroll
            for (int j = 0; j < NB; j++) {
                #pragma unroll
                for (int o = 1; o < 8; o <<= 1) {
                    az[j] += __shfl_xor_sync(0xffffffffu, az[j], o);
                    ar[j] += __shfl_xor_sync(0xffffffffu, ar[j], o);
                }
            }
            if (sub == 0) {
                const float bzv = bz[r0], brv = br[r0];
                for (int j = 0; j < nb; j++) {
                    const int node = d_order[base + j];
                    float z  = sigm(d_Yz[(size_t)node * HID + r0] + az[j] + bzv);
                    float rr = sigm(d_Yr[(size_t)node * HID + r0] + ar[j] + brv);
                    d_Z[(size_t)node * HID + r0]    = z;
                    d_Ubuf[(size_t)node * HID + r0] = sv[j][r0] * rr;
                }
            }
            __syncthreads();
        }
        grid_barrier(&gen);

        // ---- phase 2: c = tanh(whx + Uh@(ph*r)), h ----
        for (int t = blockIdx.x; t < ntasks; t += GSCAN) {
            const int group = t >> 3, chunk = t & 7;
            const int base = s + group * NB;
            const int nb = min(NB, e - base);
            for (int idx = tid; idx < NB * HID; idx += 256) {
                const int j = idx >> 8, c = idx & 255;
                float v = 0.f;
                if (j < nb) {
                    int node = d_order[base + j];
                    v = d_Ubuf[(size_t)node * HID + c];
                }
                sv[j][c] = v;
            }
            __syncthreads();
            const int r0 = chunk * 32 + rrel;
            float ah[NB];
            #pragma unroll
            for (int j = 0; j < NB; j++) ah[j] = 0.f;
            const float* uhr = Uh + (size_t)r0 * HID + sub * 4;
            #pragma unroll
            for (int k = 0; k < 8; k++) {
                const float4 a = *(const float4*)(uhr + k * 32);
                #pragma unroll
                for (int j = 0; j < NB; j++) {
                    const float4 p = *(const float4*)(&sv[j][sub * 4 + k * 32]);
                    ah[j] = fmaf(a.x, p.x, fmaf(a.y, p.y, fmaf(a.z, p.z, fmaf(a.w, p.w, ah[j]))));
                }
            }
            #pragma unroll
            for (int j = 0; j < NB; j++) {
                #pragma unroll
                for (int o = 1; o < 8; o <<= 1)
                    ah[j] += __shfl_xor_sync(0xffffffffu, ah[j], o);
            }
            if (sub == 0) {
                const float bhv = bh[r0];
                for (int j = 0; j < nb; j++) {
                    const int node = d_order[base + j];
                    float c = tanhf(d_Yh[(size_t)node * HID + r0] + ah[j] + bhv);
                    float z = d_Z[(size_t)node * HID + r0];
                    float ph = d_H[(size_t)d_par[node] * HID + r0];
                    d_H[(size_t)node * HID + r0] = z * ph + (1.f - z) * c;
                }
            }
            __syncthreads();
        }
        grid_barrier(&gen);
    }
}

// ---------------- leaf max (partial) ----------------
__global__ void leafmax(const int* __restrict__ leaf) {
    int b = blockIdx.x, tid = threadIdx.x;
    float m = -1e30f;
    for (int l = b * 128; l < (b + 1) * 128; l++) {
        int idx = leaf[l];
        m = fmaxf(m, d_H[(size_t)idx * HID + tid]);
    }
    d_Pmax[b * HID + tid] = m;
}

// ---------------- combine + W_out matvec + softmax + loss ----------------
__global__ void finalk(const float* __restrict__ y, const float* __restrict__ Wout,
                       const float* __restrict__ bout, float* __restrict__ out,
                       int out_size) {
    __shared__ float fs[HID];
    __shared__ float logits[NCLASS];
    int tid = threadIdx.x;
    float m = -1e30f;
    #pragma unroll
    for (int b = 0; b < 16; b++) m = fmaxf(m, d_Pmax[b * HID + tid]);
    fs[tid] = m;
    __syncthreads();
    if (tid < NCLASS) {
        float acc = 0.f;
        for (int h = 0; h < HID; h++) acc = fmaf(Wout[tid * HID + h], fs[h], acc);
        logits[tid] = acc + bout[tid];
    }
    __syncthreads();
    if (tid == 0) {
        float mx = logits[0];
        for (int c = 1; c < NCLASS; c++) mx = fmaxf(mx, logits[c]);
        float ex[NCLASS], ssum = 0.f;
        for (int c = 0; c < NCLASS; c++) { ex[c] = __expf(logits[c] - mx); ssum += ex[c]; }
        float loss = 0.f;
        for (int c = 0; c < NCLASS; c++) {
            float p = ex[c] / ssum;
            if (c < out_size) out[c] = p;
            float d = y[c] - p;
            loss += d * d;
        }
        if (out_size > NCLASS) out[NCLASS] = loss;
    }
}

// ---------------- launcher ----------------
extern "C" void kernel_launch(void* const* d_in, const int* in_sizes, int n_in,
                              void* d_out, int out_size) {
    const int*   tree = (const int*)d_in[0];
    const int*   edge = (const int*)d_in[1];
    const int*   leaf = (const int*)d_in[2];
    const float* y    = (const float*)d_in[3];
    const float* E    = (const float*)d_in[4];
    const float* Wz   = (const float*)d_in[5];
    const float* Uz   = (const float*)d_in[6];
    const float* bz   = (const float*)d_in[7];
    const float* Wr   = (const float*)d_in[8];
    const float* Ur   = (const float*)d_in[9];
    const float* br   = (const float*)d_in[10];
    const float* Wh   = (const float*)d_in[11];
    const float* Uh   = (const float*)d_in[12];
    const float* bh   = (const float*)d_in[13];
    const float* Wout = (const float*)d_in[14];
    const float* bout = (const float*)d_in[15];
    float* out = (float*)d_out;

    transposeE<<<dim3((VOCAB + 31) / 32, HID / 32), dim3(32, 8)>>>(E);
    gatherX<<<NN, HID>>>(tree);
    gemm3<<<dim3(NN / 128, HID / 64, 3), 256>>>(Wz, Wr, Wh);
    prep<<<1, 1024>>>(edge);
    scan_kernel<<<GSCAN, 256>>>(Uz, Ur, Uh, bz, br, bh);
    leafmax<<<16, HID>>>(leaf);
    finalk<<<1, HID>>>(y, Wout, bout, out, out_size);
}

// round 8
// speedup vs baseline: 1.7160x; 1.7160x over previous
#include <cuda_runtime.h>
#include <cuda_bf16.h>

#define NN     4096
#define WORDS  64
#define HID    256
#define VOCAB  50257
#define NCLASS 4
#define NLEAF  2048

#define NSLOT  16            // node slots
#define GSCAN  (NSLOT * 8)   // 128 persistent blocks: 8 row-chunks x 16 node slots

// ---------------- scratch (device globals; no mallocs allowed) ----------------
__device__ float d_ET[(size_t)VOCAB * HID];   // E transposed: [VOCAB][HID]
__device__ float d_X [(size_t)NN * HID];
__device__ float d_Yz[(size_t)NN * HID];
__device__ float d_Yr[(size_t)NN * HID];
__device__ float d_Yh[(size_t)NN * HID];
__device__ float d_H [(size_t)NN * HID];
__device__ float d_Z [(size_t)NN * HID];
__device__ float d_Ubuf[(size_t)NN * HID];
__device__ int   d_par[NN];
__device__ int   d_order[NN];
__device__ int   d_level_start[NN + 1];
__device__ int   d_offs[NN];
__device__ int   d_nlevels;
__device__ int   d_cnt_u[NN];   // per-node: # of chunk-blocks done with phase 1
__device__ int   d_cnt_h[NN];   // per-node: # of chunk-blocks done with phase 2
__device__ float d_Pmax[16 * HID];

// ---------------- E transpose: E(HID,VOCAB) -> ET(VOCAB,HID) ----------------
__global__ void transposeE(const float* __restrict__ E) {
    __shared__ float tile[32][33];
    int v0 = blockIdx.x * 32, h0 = blockIdx.y * 32;
    int x = threadIdx.x, y = threadIdx.y;   // 32 x 8
    #pragma unroll
    for (int i = 0; i < 32; i += 8) {
        int h = h0 + y + i, v = v0 + x;
        tile[y + i][x] = (v < VOCAB) ? E[(size_t)h * VOCAB + v] : 0.f;
    }
    __syncthreads();
    #pragma unroll
    for (int i = 0; i < 32; i += 8) {
        int v = v0 + y + i;
        if (v < VOCAB) d_ET[(size_t)v * HID + h0 + x] = tile[x][y + i];
    }
}

// ---------------- X[n,h] = sum_w ET[tree[n,w], h];  also H[0] = X[0] ----------------
__global__ void gatherX(const int* __restrict__ tree) {
    __shared__ int wv[WORDS];
    int n = blockIdx.x;
    if (threadIdx.x < WORDS) wv[threadIdx.x] = tree[n * WORDS + threadIdx.x];
    __syncthreads();
    int h = threadIdx.x;
    float acc = 0.f;
    #pragma unroll 8
    for (int w = 0; w < WORDS; w++) acc += d_ET[(size_t)wv[w] * HID + h];
    d_X[(size_t)n * HID + h] = acc;
    if (n == 0) d_H[h] = acc;   // node_h0[0] = X[0]
}

// ---------------- Y{z,r,h} = X @ W{z,r,h}^T  (4096x256 @ 256x256) ----------------
__global__ void gemm3(const float* __restrict__ Wz, const float* __restrict__ Wr,
                      const float* __restrict__ Wh) {
    const float* W = (blockIdx.z == 0) ? Wz : (blockIdx.z == 1) ? Wr : Wh;
    float* Y       = (blockIdx.z == 0) ? d_Yz : (blockIdx.z == 1) ? d_Yr : d_Yh;
    __shared__ float As[128][17];
    __shared__ float Bs[64][17];
    const int tid = threadIdx.x;
    const int tx = tid & 15, ty = tid >> 4;       // 16x16 thread grid
    const int bm = blockIdx.x, bn = blockIdx.y;
    float acc[8][4];
    #pragma unroll
    for (int i = 0; i < 8; i++)
        #pragma unroll
        for (int j = 0; j < 4; j++) acc[i][j] = 0.f;

    const int arow = tid >> 1, ac8 = (tid & 1) * 8;
    const int brow = tid >> 2, bc4 = (tid & 3) * 4;

    for (int k0 = 0; k0 < HID; k0 += 16) {
        float4 va = *(const float4*)(d_X + (size_t)(bm * 128 + arow) * HID + k0 + ac8);
        float4 vb = *(const float4*)(d_X + (size_t)(bm * 128 + arow) * HID + k0 + ac8 + 4);
        As[arow][ac8 + 0] = va.x; As[arow][ac8 + 1] = va.y;
        As[arow][ac8 + 2] = va.z; As[arow][ac8 + 3] = va.w;
        As[arow][ac8 + 4] = vb.x; As[arow][ac8 + 5] = vb.y;
        As[arow][ac8 + 6] = vb.z; As[arow][ac8 + 7] = vb.w;
        float4 wb = *(const float4*)(W + (size_t)(bn * 64 + brow) * HID + k0 + bc4);
        Bs[brow][bc4 + 0] = wb.x; Bs[brow][bc4 + 1] = wb.y;
        Bs[brow][bc4 + 2] = wb.z; Bs[brow][bc4 + 3] = wb.w;
        __syncthreads();
        #pragma unroll
        for (int kk = 0; kk < 16; kk++) {
            float a[8], b[4];
            #pragma unroll
            for (int i = 0; i < 8; i++) a[i] = As[ty * 8 + i][kk];
            #pragma unroll
            for (int j = 0; j < 4; j++) b[j] = Bs[tx * 4 + j][kk];
            #pragma unroll
            for (int i = 0; i < 8; i++)
                #pragma unroll
                for (int j = 0; j < 4; j++) acc[i][j] = fmaf(a[i], b[j], acc[i][j]);
        }
        __syncthreads();
    }
    #pragma unroll
    for (int i = 0; i < 8; i++) {
        int m = bm * 128 + ty * 8 + i;
        float4 o = make_float4(acc[i][0], acc[i][1], acc[i][2], acc[i][3]);
        *(float4*)(Y + (size_t)m * HID + bn * 64 + tx * 4) = o;
    }
}

// ---------------- prep: levels (pointer doubling) + counting sort + counter reset ----------------
__global__ void prep(const int* __restrict__ edge) {
    __shared__ int s_jump[NN];
    __shared__ int s_add[NN];
    __shared__ int s_scan[1024];
    __shared__ int s_maxl;
    const int tid = threadIdx.x;
    if (tid == 0) s_maxl = 0;
    for (int i = tid; i < NN; i += 1024) {
        int p = edge[2 * i];
        d_par[i]  = p;
        s_jump[i] = (i == 0) ? 0 : p;
        s_add[i]  = (i == 0) ? 0 : 1;
        // reset dataflow counters every launch (graph-replay safe)
        d_cnt_u[i] = 0;
        d_cnt_h[i] = (i == 0) ? 8 : 0;   // node 0's h comes from gatherX
    }
    __syncthreads();
    for (int r = 0; r < 12; r++) {
        int nj[4], na[4];
        #pragma unroll
        for (int k = 0; k < 4; k++) {
            int i = tid + k * 1024;
            int j = s_jump[i];
            nj[k] = s_jump[j];
            na[k] = s_add[i] + s_add[j];
        }
        __syncthreads();
        #pragma unroll
        for (int k = 0; k < 4; k++) {
            int i = tid + k * 1024;
            s_jump[i] = nj[k];
            s_add[i]  = na[k];
        }
        __syncthreads();
    }
    // s_add[i] == level(i). Histogram into s_jump (reused).
    for (int i = tid; i < NN; i += 1024) s_jump[i] = 0;
    __syncthreads();
    #pragma unroll
    for (int k = 0; k < 4; k++) {
        int i = tid + k * 1024;
        atomicMax(&s_maxl, s_add[i]);
        atomicAdd(&s_jump[s_add[i]], 1);
    }
    __syncthreads();
    int c0 = s_jump[4 * tid], c1 = s_jump[4 * tid + 1];
    int c2 = s_jump[4 * tid + 2], c3 = s_jump[4 * tid + 3];
    int part = c0 + c1 + c2 + c3;
    s_scan[tid] = part;
    __syncthreads();
    for (int off = 1; off < 1024; off <<= 1) {
        int v = (tid >= off) ? s_scan[tid - off] : 0;
        __syncthreads();
        s_scan[tid] += v;
        __syncthreads();
    }
    int basep = s_scan[tid] - part;
    d_level_start[4 * tid]     = basep;
    d_level_start[4 * tid + 1] = basep + c0;
    d_level_start[4 * tid + 2] = basep + c0 + c1;
    d_level_start[4 * tid + 3] = basep + c0 + c1 + c2;
    d_offs[4 * tid]     = basep;
    d_offs[4 * tid + 1] = basep + c0;
    d_offs[4 * tid + 2] = basep + c0 + c1;
    d_offs[4 * tid + 3] = basep + c0 + c1 + c2;
    if (tid == 0) d_level_start[NN] = NN;
    __syncthreads();
    #pragma unroll
    for (int k = 0; k < 4; k++) {
        int i = tid + k * 1024;
        int lvl = s_add[i];
        int pos = atomicAdd(&d_offs[lvl], 1);
        d_order[pos] = i;
    }
    if (tid == 0) d_nlevels = s_maxl + 1;
}

// ---------------- persistent dataflow GRU scan (no grid barriers) ----------------
__device__ __forceinline__ float sigm(float x) { return 1.f / (1.f + __expf(-x)); }

__device__ __forceinline__ void spin_ge8(volatile int* c) {
    while (*c < 8) { __nanosleep(20); }
}

__global__ void __launch_bounds__(256, 1)
scan_kernel(const float* __restrict__ Uz, const float* __restrict__ Ur,
            const float* __restrict__ Uh, const float* __restrict__ bz,
            const float* __restrict__ br, const float* __restrict__ bh) {
    __shared__ float sv[HID];
    const int tid   = threadIdx.x;
    const int sub   = tid & 7;          // 8 lanes per row
    const int rrel  = tid >> 3;         // 0..31 row within chunk
    const int chunk = blockIdx.x & 7;   // fixed 32-row slice for this block
    const int pslot = blockIdx.x >> 3;  // node slot 0..NSLOT-1
    const int r0    = chunk * 32 + rrel;

    // ---- preload this thread's loop-invariant U slices into registers ----
    float4 uz[8], ur[8], uh[8];
    {
        const float* uzp = Uz + (size_t)r0 * HID + sub * 4;
        const float* urp = Ur + (size_t)r0 * HID + sub * 4;
        const float* uhp = Uh + (size_t)r0 * HID + sub * 4;
        #pragma unroll
        for (int k = 0; k < 8; k++) {
            uz[k] = *(const float4*)(uzp + k * 32);
            ur[k] = *(const float4*)(urp + k * 32);
            uh[k] = *(const float4*)(uhp + k * 32);
        }
    }
    const float bzv = bz[r0], brv = br[r0], bhv = bh[r0];
    const int nlev = d_nlevels;

    for (int L = 1; L < nlev; L++) {
        const int s = d_level_start[L];
        const int e = d_level_start[L + 1];
        const int W = e - s;

        // ================= phase 1: z, r, u = ph*r (my slot's nodes) =================
        for (int i = pslot; i < W; i += NSLOT) {
            const int n = d_order[s + i];
            const int p = d_par[n];
            // prefetch (independent of parent readiness)
            float yz = 0.f, yr = 0.f;
            if (sub == 0) {
                yz = d_Yz[(size_t)n * HID + r0];
                yr = d_Yr[(size_t)n * HID + r0];
            }
            if (tid == 0) {
                spin_ge8(&d_cnt_h[p]);
                __threadfence();   // acquire
            }
            __syncthreads();
            sv[tid] = d_H[(size_t)p * HID + tid];
            __syncthreads();

            float az = 0.f, ar = 0.f;
            #pragma unroll
            for (int k = 0; k < 8; k++) {
                const float4 pv = *(const float4*)(&sv[sub * 4 + k * 32]);
                az = fmaf(uz[k].x, pv.x, fmaf(uz[k].y, pv.y, fmaf(uz[k].z, pv.z, fmaf(uz[k].w, pv.w, az))));
                ar = fmaf(ur[k].x, pv.x, fmaf(ur[k].y, pv.y, fmaf(ur[k].z, pv.z, fmaf(ur[k].w, pv.w, ar))));
            }
            #pragma unroll
            for (int o = 1; o < 8; o <<= 1) {
                az += __shfl_xor_sync(0xffffffffu, az, o);
                ar += __shfl_xor_sync(0xffffffffu, ar, o);
            }
            if (sub == 0) {
                float z  = sigm(yz + az + bzv);
                float rr = sigm(yr + ar + brv);
                d_Z[(size_t)n * HID + r0]    = z;
                d_Ubuf[(size_t)n * HID + r0] = sv[r0] * rr;
            }
            __syncthreads();           // all 32 row-writers done
            if (tid == 0) {
                __threadfence();       // release
                atomicAdd(&d_cnt_u[n], 1);
            }
        }

        // ================= phase 2: c = tanh(.); h = z*ph + (1-z)*c =================
        for (int i = pslot; i < W; i += NSLOT) {
            const int n = d_order[s + i];
            const int p = d_par[n];
            float yh = 0.f, zv = 0.f, ph = 0.f;
            if (sub == 0) {
                yh = d_Yh[(size_t)n * HID + r0];
                zv = d_Z [(size_t)n * HID + r0];   // written by this very block in phase 1
                ph = d_H [(size_t)p * HID + r0];   // visible since phase 1 acquired it
            }
            if (tid == 0) {
                spin_ge8(&d_cnt_u[n]);
                __threadfence();   // acquire
            }
            __syncthreads();
            sv[tid] = d_Ubuf[(size_t)n * HID + tid];
            __syncthreads();

            float ah = 0.f;
            #pragma unroll
            for (int k = 0; k < 8; k++) {
                const float4 pv = *(const float4*)(&sv[sub * 4 + k * 32]);
                ah = fmaf(uh[k].x, pv.x, fmaf(uh[k].y, pv.y, fmaf(uh[k].z, pv.z, fmaf(uh[k].w, pv.w, ah))));
            }
            #pragma unroll
            for (int o = 1; o < 8; o <<= 1)
                ah += __shfl_xor_sync(0xffffffffu, ah, o);

            if (sub == 0) {
                float c = tanhf(yh + ah + bhv);
                d_H[(size_t)n * HID + r0] = zv * ph + (1.f - zv) * c;
            }
            __syncthreads();
            if (tid == 0) {
                __threadfence();       // release
                atomicAdd(&d_cnt_h[n], 1);
            }
        }
    }
}

// ---------------- leaf max (partial) ----------------
__global__ void leafmax(const int* __restrict__ leaf) {
    int b = blockIdx.x, tid = threadIdx.x;
    float m = -1e30f;
    for (int l = b * 128; l < (b + 1) * 128; l++) {
        int idx = leaf[l];
        m = fmaxf(m, d_H[(size_t)idx * HID + tid]);
    }
    d_Pmax[b * HID + tid] = m;
}

// ---------------- combine + W_out matvec + softmax + loss ----------------
__global__ void finalk(const float* __restrict__ y, const float* __restrict__ Wout,
                       const float* __restrict__ bout, float* __restrict__ out,
                       int out_size) {
    __shared__ float fs[HID];
    __shared__ float logits[NCLASS];
    int tid = threadIdx.x;
    float m = -1e30f;
    #pragma unroll
    for (int b = 0; b < 16; b++) m = fmaxf(m, d_Pmax[b * HID + tid]);
    fs[tid] = m;
    __syncthreads();
    if (tid < NCLASS) {
        float acc = 0.f;
        for (int h = 0; h < HID; h++) acc = fmaf(Wout[tid * HID + h], fs[h], acc);
        logits[tid] = acc + bout[tid];
    }
    __syncthreads();
    if (tid == 0) {
        float mx = logits[0];
        for (int c = 1; c < NCLASS; c++) mx = fmaxf(mx, logits[c]);
        float ex[NCLASS], ssum = 0.f;
        for (int c = 0; c < NCLASS; c++) { ex[c] = __expf(logits[c] - mx); ssum += ex[c]; }
        float loss = 0.f;
        for (int c = 0; c < NCLASS; c++) {
            float p = ex[c] / ssum;
            if (c < out_size) out[c] = p;
            float d = y[c] - p;
            loss += d * d;
        }
        if (out_size > NCLASS) out[NCLASS] = loss;
    }
}

// ---------------- launcher ----------------
extern "C" void kernel_launch(void* const* d_in, const int* in_sizes, int n_in,
                              void* d_out, int out_size) {
    const int*   tree = (const int*)d_in[0];
    const int*   edge = (const int*)d_in[1];
    const int*   leaf = (const int*)d_in[2];
    const float* y    = (const float*)d_in[3];
    const float* E    = (const float*)d_in[4];
    const float* Wz   = (const float*)d_in[5];
    const float* Uz   = (const float*)d_in[6];
    const float* bz   = (const float*)d_in[7];
    const float* Wr   = (const float*)d_in[8];
    const float* Ur   = (const float*)d_in[9];
    const float* br   = (const float*)d_in[10];
    const float* Wh   = (const float*)d_in[11];
    const float* Uh   = (const float*)d_in[12];
    const float* bh   = (const float*)d_in[13];
    const float* Wout = (const float*)d_in[14];
    const float* bout = (const float*)d_in[15];
    float* out = (float*)d_out;

    transposeE<<<dim3((VOCAB + 31) / 32, HID / 32), dim3(32, 8)>>>(E);
    gatherX<<<NN, HID>>>(tree);
    gemm3<<<dim3(NN / 128, HID / 64, 3), 256>>>(Wz, Wr, Wh);
    prep<<<1, 1024>>>(edge);
    scan_kernel<<<GSCAN, 256>>>(Uz, Ur, Uh, bz, br, bh);
    leafmax<<<16, HID>>>(leaf);
    finalk<<<1, HID>>>(y, Wout, bout, out, out_size);
}